// round 1
// baseline (speedup 1.0000x reference)
#include <cuda_runtime.h>

#define Hh 64
#define Ww 64
#define Bb 32
#define CIN 16
#define COUT 32
#define Pp 144           // CIN * 3 * 3
#define PS 145           // padded smem row stride (odd -> conflict-free strided access)

__global__ __launch_bounds__(64) void xonv_kernel(
    const float* __restrict__ x,        // (B, CIN, H, W)
    const float* __restrict__ weights,  // (H, W, COUT, CIN, 3, 3)
    const float* __restrict__ bias,     // (H, W, COUT)
    float* __restrict__ out)            // (B, COUT, H, W)
{
    __shared__ float ws[COUT][PS];
    __shared__ float xs[Bb][PS];
    __shared__ float bs[COUT];

    const int loc = blockIdx.x;          // 0..4095
    const int h   = loc >> 6;
    const int w   = loc & 63;
    const int tid = threadIdx.x;         // 0..63

    // ---------------- stage weights: 4608 floats = 1152 float4, coalesced ----------------
    const float4* wg = (const float4*)(weights + (size_t)loc * (COUT * Pp));
    #pragma unroll
    for (int i = 0; i < 18; ++i) {
        int g = tid + i * 64;            // 0..1151
        float4 v = wg[g];
        int o = g / 36;
        int c = (g % 36) * 4;
        ws[o][c]     = v.x;
        ws[o][c + 1] = v.y;
        ws[o][c + 2] = v.z;
        ws[o][c + 3] = v.w;
    }
    if (tid < COUT) bs[tid] = bias[loc * COUT + tid];

    // ---------------- stage x patches: task = (b, ci, kh), 3 floats each ----------------
    // p layout: p = ci*9 + kh*3 + kw  (channel slowest, matching reference im2col)
    #pragma unroll
    for (int i = 0; i < 24; ++i) {
        int t  = tid + i * 64;           // 0..1535
        int kh = t % 3;
        int ci = (t / 3) % CIN;
        int b  = t / (3 * CIN);
        int hh = h + kh - 1;
        float v0 = 0.f, v1 = 0.f, v2 = 0.f;
        if ((unsigned)hh < (unsigned)Hh) {
            const float* xrow = x + (((size_t)b * CIN + ci) * Hh + hh) * Ww;
            if (w > 0)      v0 = xrow[w - 1];
            v1 = xrow[w];
            if (w < Ww - 1) v2 = xrow[w + 1];
        }
        int p = ci * 9 + kh * 3;
        xs[b][p]     = v0;
        xs[b][p + 1] = v1;
        xs[b][p + 2] = v2;
    }
    __syncthreads();

    // ---------------- compute: each thread does a 4b x 4o tile over K=144 ----------------
    const int tx = tid & 7;              // o-tile index: o = tx*4 .. tx*4+3
    const int ty = tid >> 3;             // b-tile index: b = ty*4 .. ty*4+3
    const int ob = tx * 4;
    const int bb = ty * 4;

    float acc[4][4];
    #pragma unroll
    for (int i = 0; i < 4; ++i)
        #pragma unroll
        for (int j = 0; j < 4; ++j)
            acc[i][j] = 0.f;

    const float* wp = &ws[ob][0];
    const float* xp = &xs[bb][0];

    #pragma unroll 8
    for (int p = 0; p < Pp; ++p) {
        float w0 = wp[p];
        float w1 = wp[PS + p];
        float w2 = wp[2 * PS + p];
        float w3 = wp[3 * PS + p];
        float x0 = xp[p];
        float x1 = xp[PS + p];
        float x2 = xp[2 * PS + p];
        float x3 = xp[3 * PS + p];
        acc[0][0] += x0 * w0; acc[0][1] += x0 * w1; acc[0][2] += x0 * w2; acc[0][3] += x0 * w3;
        acc[1][0] += x1 * w0; acc[1][1] += x1 * w1; acc[1][2] += x1 * w2; acc[1][3] += x1 * w3;
        acc[2][0] += x2 * w0; acc[2][1] += x2 * w1; acc[2][2] += x2 * w2; acc[2][3] += x2 * w3;
        acc[3][0] += x3 * w0; acc[3][1] += x3 * w1; acc[3][2] += x3 * w2; acc[3][3] += x3 * w3;
    }

    // ---------------- epilogue: out[b][o][h][w] = acc + bias[h][w][o] ----------------
    #pragma unroll
    for (int i = 0; i < 4; ++i) {
        int b_ = bb + i;
        #pragma unroll
        for (int j = 0; j < 4; ++j) {
            int o_ = ob + j;
            out[((size_t)b_ * COUT + o_) * (Hh * Ww) + loc] = acc[i][j] + bs[o_];
        }
    }
}

extern "C" void kernel_launch(void* const* d_in, const int* in_sizes, int n_in,
                              void* d_out, int out_size) {
    const float* x       = (const float*)d_in[0];
    const float* weights = (const float*)d_in[1];
    const float* bias    = (const float*)d_in[2];
    float* out = (float*)d_out;
    (void)in_sizes; (void)n_in; (void)out_size;

    xonv_kernel<<<Hh * Ww, 64>>>(x, weights, bias, out);
}